// round 2
// baseline (speedup 1.0000x reference)
#include <cuda_runtime.h>
#include <cuda.h>
#include <cstdint>

// ============================================================================
// LoRALinear: out[T,4096] = x[T,4096] @ (W + a*A@B^T)^T + b
// sm_103 baseline ISA only (no tcgen05 / no 'a'-suffix features):
//   kernel 1: Weff = W + alpha*A@B^T  (rounded rna to tf32)
//   kernel 2: tf32 mma.sync GEMM, cp.async 4-stage pipeline
// ============================================================================
#define KDIM 4096
#define MDIM 4096
#define RANK 8
#define LORA_ALPHA (8.0f / RANK)

#define TILE_M 128
#define TILE_N 128
#define KC 32
#define NSTAGES 4
#define LDS_STRIDE 36                       // 32 + 4 pad floats -> conflict-free frags

#define A_TILE_FLOATS (TILE_M * LDS_STRIDE) // 4608
#define B_TILE_FLOATS (TILE_N * LDS_STRIDE)
#define STAGE_FLOATS  (A_TILE_FLOATS + B_TILE_FLOATS)   // 9216
#define SMEM_BYTES    (NSTAGES * STAGE_FLOATS * 4)      // 147456

// 64MB scratch for Weff (row-major [MDIM, KDIM])
__device__ float g_Weff[(size_t)MDIM * (size_t)KDIM];

// ============================================================================
// Kernel 1: Weff = rna_tf32(W + alpha * A @ B^T)
// ============================================================================
__device__ __forceinline__ uint32_t f2tf32(float f) {
    uint32_t o;
    asm("cvt.rna.tf32.f32 %0, %1;" : "=r"(o) : "f"(f));
    return o;
}

__global__ void __launch_bounds__(256)
weff_prep_kernel(const float* __restrict__ W, const float* __restrict__ A,
                 const float* __restrict__ Bm, uint32_t* __restrict__ Weff) {
    int i = blockIdx.x * blockDim.x + threadIdx.x;   // float4 index
    int m  = i >> 10;                                // / (KDIM/4)
    int kq = i & 1023;
    const float4* Arow = (const float4*)(A + (size_t)m * RANK);
    float4 a0 = Arow[0], a1 = Arow[1];
    float4 w = ((const float4*)W)[i];
    float r[4];
#pragma unroll
    for (int j = 0; j < 4; j++) {
        const float4* Brow = (const float4*)(Bm + (size_t)(kq * 4 + j) * RANK);
        float4 b0 = Brow[0], b1 = Brow[1];
        r[j] = a0.x * b0.x + a0.y * b0.y + a0.z * b0.z + a0.w * b0.w
             + a1.x * b1.x + a1.y * b1.y + a1.z * b1.z + a1.w * b1.w;
    }
    uint4 o;
    o.x = f2tf32(w.x + LORA_ALPHA * r[0]);
    o.y = f2tf32(w.y + LORA_ALPHA * r[1]);
    o.z = f2tf32(w.z + LORA_ALPHA * r[2]);
    o.w = f2tf32(w.w + LORA_ALPHA * r[3]);
    ((uint4*)Weff)[i] = o;
}

// ============================================================================
// Kernel 2: C = x @ Weff^T + b   (tf32 mma.sync, cp.async pipeline)
// ============================================================================
__device__ __forceinline__ void cp16(uint32_t dst_smem, const void* src) {
    asm volatile("cp.async.cg.shared.global [%0], [%1], 16;"
                 :: "r"(dst_smem), "l"(src) : "memory");
}
#define CP_COMMIT() asm volatile("cp.async.commit_group;" ::: "memory")
#define CP_WAIT(n)  asm volatile("cp.async.wait_group %0;" :: "n"(n) : "memory")

__device__ __forceinline__ void mma_tf32(float c[4], const uint32_t a[4],
                                         const uint32_t b[2]) {
    asm volatile(
        "mma.sync.aligned.m16n8k8.row.col.f32.tf32.tf32.f32 "
        "{%0,%1,%2,%3}, {%4,%5,%6,%7}, {%8,%9}, {%0,%1,%2,%3};"
        : "+f"(c[0]), "+f"(c[1]), "+f"(c[2]), "+f"(c[3])
        : "r"(a[0]), "r"(a[1]), "r"(a[2]), "r"(a[3]), "r"(b[0]), "r"(b[1]));
}

__global__ void __launch_bounds__(256, 1)
lora_gemm_kernel(const float* __restrict__ x, const uint32_t* __restrict__ Weff,
                 const float* __restrict__ bias, float* __restrict__ out,
                 int KITERS) {
    extern __shared__ float smem[];
    uint32_t smem_u32;
    asm("{ .reg .u64 t; cvta.to.shared.u64 t, %1; cvt.u32.u64 %0, t; }"
        : "=r"(smem_u32) : "l"(smem));

    const int tid = threadIdx.x;
    const int wid = tid >> 5;
    const int lid = tid & 31;
    const int gid = lid >> 2;    // 0..7
    const int qid = lid & 3;     // 0..3

    const int n0 = blockIdx.x * TILE_N;   // output columns (fast grid dim)
    const int m0 = blockIdx.y * TILE_M;   // token rows

    const int wm0 = (wid & 1) * 64;       // warp M offset in tile
    const int wn0 = (wid >> 1) * 32;      // warp N offset in tile

    // --- cp.async copy plan: 2048 x 16B chunks per stage, 8 per thread ---
    // chunk id c in [0,1024): A tile row c/8, 16B-col c%8
    //          c in [1024,2048): B tile
    const float* gA = x + (size_t)m0 * KDIM;
    const float* gB = (const float*)Weff + (size_t)n0 * KDIM;

    auto issue_stage = [&](int kc, int slot) {
        uint32_t sA = smem_u32 + slot * STAGE_FLOATS * 4;
        uint32_t sB = sA + A_TILE_FLOATS * 4;
        const float* srcA = gA + kc * KC;
        const float* srcB = gB + kc * KC;
#pragma unroll
        for (int c = 0; c < 4; c++) {
            int id = tid + c * 256;            // 0..1023 : A
            int row = id >> 3, c4 = id & 7;
            cp16(sA + (row * LDS_STRIDE + c4 * 4) * 4,
                 srcA + (size_t)row * KDIM + c4 * 4);
        }
#pragma unroll
        for (int c = 0; c < 4; c++) {
            int id = tid + c * 256;
            int row = id >> 3, c4 = id & 7;
            cp16(sB + (row * LDS_STRIDE + c4 * 4) * 4,
                 srcB + (size_t)row * KDIM + c4 * 4);
        }
    };

    float acc[4][4][4];
#pragma unroll
    for (int i = 0; i < 4; i++)
#pragma unroll
        for (int j = 0; j < 4; j++)
#pragma unroll
            for (int e = 0; e < 4; e++) acc[i][j][e] = 0.0f;

    // prologue: stages 0..NSTAGES-2
#pragma unroll
    for (int s = 0; s < NSTAGES - 1; s++) {
        issue_stage(s, s);
        CP_COMMIT();
    }

    const uint32_t* As_all = (const uint32_t*)smem;
#pragma unroll 1
    for (int kc = 0; kc < KITERS; kc++) {
        CP_WAIT(NSTAGES - 2);
        __syncthreads();

        int nxt = kc + NSTAGES - 1;
        if (nxt < KITERS) issue_stage(nxt, nxt & (NSTAGES - 1));
        CP_COMMIT();

        int slot = kc & (NSTAGES - 1);
        const uint32_t* As = As_all + slot * STAGE_FLOATS;
        const uint32_t* Bs = As + A_TILE_FLOATS;

#pragma unroll
        for (int k8 = 0; k8 < 4; k8++) {
            const int kb = k8 * 8;
            uint32_t af[4][4], bf[4][2];
#pragma unroll
            for (int i = 0; i < 4; i++) {
                int r = wm0 + i * 16 + gid;
                af[i][0] = As[r * LDS_STRIDE + kb + qid];
                af[i][1] = As[(r + 8) * LDS_STRIDE + kb + qid];
                af[i][2] = As[r * LDS_STRIDE + kb + qid + 4];
                af[i][3] = As[(r + 8) * LDS_STRIDE + kb + qid + 4];
            }
#pragma unroll
            for (int j = 0; j < 4; j++) {
                int n = wn0 + j * 8 + gid;
                bf[j][0] = Bs[n * LDS_STRIDE + kb + qid];
                bf[j][1] = Bs[n * LDS_STRIDE + kb + qid + 4];
            }
#pragma unroll
            for (int i = 0; i < 4; i++)
#pragma unroll
                for (int j = 0; j < 4; j++)
                    mma_tf32(acc[i][j], af[i], bf[j]);
        }
    }

    // --- epilogue: acc + bias -> out ---
#pragma unroll
    for (int j = 0; j < 4; j++) {
        int col = n0 + wn0 + j * 8 + qid * 2;
        float2 bb = *(const float2*)(bias + col);
#pragma unroll
        for (int i = 0; i < 4; i++) {
            int row = m0 + wm0 + i * 16 + gid;
            float2 v0 = make_float2(acc[i][j][0] + bb.x, acc[i][j][1] + bb.y);
            float2 v1 = make_float2(acc[i][j][2] + bb.x, acc[i][j][3] + bb.y);
            *(float2*)(out + (size_t)row * MDIM + col) = v0;
            *(float2*)(out + (size_t)(row + 8) * MDIM + col) = v1;
        }
    }
}

// ============================================================================
// Host launch
// ============================================================================
extern "C" void kernel_launch(void* const* d_in, const int* in_sizes, int n_in,
                              void* d_out, int out_size) {
    const float* x = (const float*)d_in[0];   // [T, 4096]
    const float* W = (const float*)d_in[1];   // [4096, 4096]
    const float* b = (const float*)d_in[2];   // [4096]
    const float* A = (const float*)d_in[3];   // [4096, 8]
    const float* B = (const float*)d_in[4];   // [4096, 8]
    float* out = (float*)d_out;               // [T, 4096]
    int T = in_sizes[0] / KDIM;

    void* weff_ptr = nullptr;
    cudaGetSymbolAddress(&weff_ptr, g_Weff);

    int quads = (MDIM * KDIM) / 4;
    weff_prep_kernel<<<quads / 256, 256>>>(W, A, B, (uint32_t*)weff_ptr);

    cudaFuncSetAttribute(lora_gemm_kernel,
                         cudaFuncAttributeMaxDynamicSharedMemorySize, SMEM_BYTES);

    dim3 grid(MDIM / TILE_N, T / TILE_M);   // (32, T/128) — n fastest for L2 reuse
    lora_gemm_kernel<<<grid, 256, SMEM_BYTES>>>(
        x, (const uint32_t*)weff_ptr, b, out, KDIM / KC);
}

// round 3
// speedup vs baseline: 1.0271x; 1.0271x over previous
#include <cuda_runtime.h>
#include <cuda.h>
#include <cstdint>

// ============================================================================
// LoRALinear: out[T,4096] = x[T,4096] @ (W + a*A@B^T)^T + b
// sm_103 baseline ISA (no tcgen05):
//   kernel 1: Weff = rna_tf32(W + alpha*A@B^T)
//   kernel 2: tf32 mma.sync GEMM, cp.async 4-stage pipeline,
//             ldmatrix fragment loads + fragment double-buffering
// ============================================================================
#define KDIM 4096
#define MDIM 4096
#define RANK 8
#define LORA_ALPHA (8.0f / RANK)

#define TILE_M 128
#define TILE_N 128
#define KC 32
#define NSTAGES 4
#define LDS_STRIDE 36                       // 32 + 4 pad floats

#define A_TILE_FLOATS (TILE_M * LDS_STRIDE) // 4608
#define B_TILE_FLOATS (TILE_N * LDS_STRIDE)
#define STAGE_FLOATS  (A_TILE_FLOATS + B_TILE_FLOATS)   // 9216
#define SMEM_BYTES    (NSTAGES * STAGE_FLOATS * 4)      // 147456

__device__ float g_Weff[(size_t)MDIM * (size_t)KDIM];

// ============================================================================
// Kernel 1: Weff = rna_tf32(W + alpha * A @ B^T)
// ============================================================================
__device__ __forceinline__ uint32_t f2tf32(float f) {
    uint32_t o;
    asm("cvt.rna.tf32.f32 %0, %1;" : "=r"(o) : "f"(f));
    return o;
}

__global__ void __launch_bounds__(256)
weff_prep_kernel(const float* __restrict__ W, const float* __restrict__ A,
                 const float* __restrict__ Bm, uint32_t* __restrict__ Weff) {
    int i = blockIdx.x * blockDim.x + threadIdx.x;   // float4 index
    int m  = i >> 10;
    int kq = i & 1023;
    const float4* Arow = (const float4*)(A + (size_t)m * RANK);
    float4 a0 = Arow[0], a1 = Arow[1];
    float4 w = ((const float4*)W)[i];
    float r[4];
#pragma unroll
    for (int j = 0; j < 4; j++) {
        const float4* Brow = (const float4*)(Bm + (size_t)(kq * 4 + j) * RANK);
        float4 b0 = Brow[0], b1 = Brow[1];
        r[j] = a0.x * b0.x + a0.y * b0.y + a0.z * b0.z + a0.w * b0.w
             + a1.x * b1.x + a1.y * b1.y + a1.z * b1.z + a1.w * b1.w;
    }
    uint4 o;
    o.x = f2tf32(w.x + LORA_ALPHA * r[0]);
    o.y = f2tf32(w.y + LORA_ALPHA * r[1]);
    o.z = f2tf32(w.z + LORA_ALPHA * r[2]);
    o.w = f2tf32(w.w + LORA_ALPHA * r[3]);
    ((uint4*)Weff)[i] = o;
}

// ============================================================================
// Kernel 2: C = x @ Weff^T + b
// ============================================================================
__device__ __forceinline__ void cp16(uint32_t dst_smem, const void* src) {
    asm volatile("cp.async.cg.shared.global [%0], [%1], 16;"
                 :: "r"(dst_smem), "l"(src) : "memory");
}
#define CP_COMMIT() asm volatile("cp.async.commit_group;" ::: "memory")
#define CP_WAIT(n)  asm volatile("cp.async.wait_group %0;" :: "n"(n) : "memory")

__device__ __forceinline__ void mma_tf32(float c[4], const uint32_t a[4],
                                         const uint32_t b[2]) {
    asm volatile(
        "mma.sync.aligned.m16n8k8.row.col.f32.tf32.tf32.f32 "
        "{%0,%1,%2,%3}, {%4,%5,%6,%7}, {%8,%9}, {%0,%1,%2,%3};"
        : "+f"(c[0]), "+f"(c[1]), "+f"(c[2]), "+f"(c[3])
        : "r"(a[0]), "r"(a[1]), "r"(a[2]), "r"(a[3]), "r"(b[0]), "r"(b[1]));
}

__device__ __forceinline__ void ldsm4(uint32_t r[4], uint32_t addr) {
    asm volatile("ldmatrix.sync.aligned.m8n8.x4.shared.b16 {%0,%1,%2,%3}, [%4];"
                 : "=r"(r[0]), "=r"(r[1]), "=r"(r[2]), "=r"(r[3]) : "r"(addr));
}

struct Frags {
    uint32_t a[4][4];
    uint32_t b[4][2];
};

__global__ void __launch_bounds__(256, 1)
lora_gemm_kernel(const float* __restrict__ x, const uint32_t* __restrict__ Weff,
                 const float* __restrict__ bias, float* __restrict__ out,
                 int KITERS) {
    extern __shared__ float smem[];
    uint32_t smem_u32;
    asm("{ .reg .u64 t; cvta.to.shared.u64 t, %1; cvt.u32.u64 %0, t; }"
        : "=r"(smem_u32) : "l"(smem));

    const int tid = threadIdx.x;
    const int wid = tid >> 5;
    const int lid = tid & 31;
    const int gid = lid >> 2;    // 0..7
    const int qid = lid & 3;     // 0..3

    const int n0 = blockIdx.x * TILE_N;
    const int m0 = blockIdx.y * TILE_M;

    const int wm0 = (wid & 1) * 64;       // warp M offset
    const int wn0 = (wid >> 1) * 32;      // warp N offset

    // ---- ldmatrix per-lane row/col offsets (in floats within a tile) ----
    // A x4 for af[i]: matrices {rows+0..7,kb}{rows+8..15,kb}{+0..7,kb+4}{+8..15,kb+4}
    const int a_row  = wm0 + (lid & 15);       // + i*16
    const int a_koff = (lid >> 4) * 4;         // 0 or 4
    // B x4 covers j-pair p (j=2p, 2p+1):
    //   matrices {n=j*8.., kb}{j*8.., kb+4}{(j+1)*8.., kb}{(j+1)*8.., kb+4}
    const int b_row  = wn0 + (lid & 7) + ((lid >> 4) * 8);  // + p*16
    const int b_koff = ((lid >> 3) & 1) * 4;

    const float* gA = x + (size_t)m0 * KDIM;
    const float* gB = (const float*)Weff + (size_t)n0 * KDIM;

    auto issue_stage = [&](int kc, int slot) {
        uint32_t sA = smem_u32 + slot * STAGE_FLOATS * 4;
        uint32_t sB = sA + A_TILE_FLOATS * 4;
        const float* srcA = gA + kc * KC;
        const float* srcB = gB + kc * KC;
#pragma unroll
        for (int c = 0; c < 4; c++) {
            int id = tid + c * 256;
            int row = id >> 3, c4 = id & 7;
            cp16(sA + (row * LDS_STRIDE + c4 * 4) * 4,
                 srcA + (size_t)row * KDIM + c4 * 4);
        }
#pragma unroll
        for (int c = 0; c < 4; c++) {
            int id = tid + c * 256;
            int row = id >> 3, c4 = id & 7;
            cp16(sB + (row * LDS_STRIDE + c4 * 4) * 4,
                 srcB + (size_t)row * KDIM + c4 * 4);
        }
    };

    auto load_frags = [&](Frags& f, uint32_t sA, uint32_t sB, int kb) {
#pragma unroll
        for (int i = 0; i < 4; i++)
            ldsm4(f.a[i], sA + ((a_row + i * 16) * LDS_STRIDE + kb + a_koff) * 4);
#pragma unroll
        for (int p = 0; p < 2; p++) {
            uint32_t t[4];
            ldsm4(t, sB + ((b_row + p * 16) * LDS_STRIDE + kb + b_koff) * 4);
            f.b[2 * p][0]     = t[0];
            f.b[2 * p][1]     = t[1];
            f.b[2 * p + 1][0] = t[2];
            f.b[2 * p + 1][1] = t[3];
        }
    };

    float acc[4][4][4];
#pragma unroll
    for (int i = 0; i < 4; i++)
#pragma unroll
        for (int j = 0; j < 4; j++)
#pragma unroll
            for (int e = 0; e < 4; e++) acc[i][j][e] = 0.0f;

#pragma unroll
    for (int s = 0; s < NSTAGES - 1; s++) {
        issue_stage(s, s);
        CP_COMMIT();
    }

    Frags fr[2];

#pragma unroll 1
    for (int kc = 0; kc < KITERS; kc++) {
        CP_WAIT(NSTAGES - 2);
        __syncthreads();

        int nxt = kc + NSTAGES - 1;
        if (nxt < KITERS) issue_stage(nxt, nxt & (NSTAGES - 1));
        CP_COMMIT();

        int slot = kc & (NSTAGES - 1);
        uint32_t sA = smem_u32 + slot * STAGE_FLOATS * 4;
        uint32_t sB = sA + A_TILE_FLOATS * 4;

        load_frags(fr[0], sA, sB, 0);
#pragma unroll
        for (int k8 = 0; k8 < 4; k8++) {
            if (k8 < 3) load_frags(fr[(k8 + 1) & 1], sA, sB, (k8 + 1) * 8);
            Frags& f = fr[k8 & 1];
#pragma unroll
            for (int i = 0; i < 4; i++)
#pragma unroll
                for (int j = 0; j < 4; j++)
                    mma_tf32(acc[i][j], f.a[i], f.b[j]);
        }
    }

    // --- epilogue: acc + bias -> out ---
#pragma unroll
    for (int j = 0; j < 4; j++) {
        int col = n0 + wn0 + j * 8 + qid * 2;
        float2 bb = *(const float2*)(bias + col);
#pragma unroll
        for (int i = 0; i < 4; i++) {
            int row = m0 + wm0 + i * 16 + gid;
            float2 v0 = make_float2(acc[i][j][0] + bb.x, acc[i][j][1] + bb.y);
            float2 v1 = make_float2(acc[i][j][2] + bb.x, acc[i][j][3] + bb.y);
            *(float2*)(out + (size_t)row * MDIM + col) = v0;
            *(float2*)(out + (size_t)(row + 8) * MDIM + col) = v1;
        }
    }
}

// ============================================================================
// Host launch
// ============================================================================
extern "C" void kernel_launch(void* const* d_in, const int* in_sizes, int n_in,
                              void* d_out, int out_size) {
    const float* x = (const float*)d_in[0];
    const float* W = (const float*)d_in[1];
    const float* b = (const float*)d_in[2];
    const float* A = (const float*)d_in[3];
    const float* B = (const float*)d_in[4];
    float* out = (float*)d_out;
    int T = in_sizes[0] / KDIM;

    void* weff_ptr = nullptr;
    cudaGetSymbolAddress(&weff_ptr, g_Weff);

    int quads = (MDIM * KDIM) / 4;
    weff_prep_kernel<<<quads / 256, 256>>>(W, A, B, (uint32_t*)weff_ptr);

    cudaFuncSetAttribute(lora_gemm_kernel,
                         cudaFuncAttributeMaxDynamicSharedMemorySize, SMEM_BYTES);

    dim3 grid(MDIM / TILE_N, T / TILE_M);   // n fastest for L2 reuse
    lora_gemm_kernel<<<grid, 256, SMEM_BYTES>>>(
        x, (const uint32_t*)weff_ptr, b, out, KDIM / KC);
}

// round 4
// speedup vs baseline: 1.2274x; 1.1950x over previous
#include <cuda_runtime.h>
#include <cuda.h>
#include <cstdint>

// ============================================================================
// LoRALinear: out[T,4096] = x[T,4096] @ (W + a*A@B^T)^T + b
// sm_103 baseline ISA (no tcgen05):
//   kernel 1: Weff = rna_tf32(W + alpha*A@B^T)
//   kernel 2: tf32 mma.sync GEMM, cp.async 3-stage pipeline, ldmatrix frags,
//             512 threads/CTA (4 warps/SMSP) for latency hiding
// ============================================================================
#define KDIM 4096
#define MDIM 4096
#define RANK 8
#define LORA_ALPHA (8.0f / RANK)

#define TILE_M 128
#define TILE_N 256
#define KC 32
#define NSTAGES 3
#define NTHREADS 512
#define LDS_STRIDE 36                       // 32 + 4 pad floats

#define A_TILE_FLOATS (TILE_M * LDS_STRIDE) // 4608
#define B_TILE_FLOATS (TILE_N * LDS_STRIDE) // 9216
#define STAGE_FLOATS  (A_TILE_FLOATS + B_TILE_FLOATS)   // 13824
#define SMEM_BYTES    (NSTAGES * STAGE_FLOATS * 4)      // 165888

__device__ float g_Weff[(size_t)MDIM * (size_t)KDIM];

// ============================================================================
// Kernel 1: Weff = rna_tf32(W + alpha * A @ B^T)
// ============================================================================
__device__ __forceinline__ uint32_t f2tf32(float f) {
    uint32_t o;
    asm("cvt.rna.tf32.f32 %0, %1;" : "=r"(o) : "f"(f));
    return o;
}

__global__ void __launch_bounds__(256)
weff_prep_kernel(const float* __restrict__ W, const float* __restrict__ A,
                 const float* __restrict__ Bm, uint32_t* __restrict__ Weff) {
    int i = blockIdx.x * blockDim.x + threadIdx.x;   // float4 index
    int m  = i >> 10;
    int kq = i & 1023;
    const float4* Arow = (const float4*)(A + (size_t)m * RANK);
    float4 a0 = Arow[0], a1 = Arow[1];
    float4 w = ((const float4*)W)[i];
    float r[4];
#pragma unroll
    for (int j = 0; j < 4; j++) {
        const float4* Brow = (const float4*)(Bm + (size_t)(kq * 4 + j) * RANK);
        float4 b0 = Brow[0], b1 = Brow[1];
        r[j] = a0.x * b0.x + a0.y * b0.y + a0.z * b0.z + a0.w * b0.w
             + a1.x * b1.x + a1.y * b1.y + a1.z * b1.z + a1.w * b1.w;
    }
    uint4 o;
    o.x = f2tf32(w.x + LORA_ALPHA * r[0]);
    o.y = f2tf32(w.y + LORA_ALPHA * r[1]);
    o.z = f2tf32(w.z + LORA_ALPHA * r[2]);
    o.w = f2tf32(w.w + LORA_ALPHA * r[3]);
    ((uint4*)Weff)[i] = o;
}

// ============================================================================
// Kernel 2: C = x @ Weff^T + b
// ============================================================================
__device__ __forceinline__ void cp16(uint32_t dst_smem, const void* src) {
    asm volatile("cp.async.cg.shared.global [%0], [%1], 16;"
                 :: "r"(dst_smem), "l"(src) : "memory");
}
#define CP_COMMIT() asm volatile("cp.async.commit_group;" ::: "memory")
#define CP_WAIT(n)  asm volatile("cp.async.wait_group %0;" :: "n"(n) : "memory")

__device__ __forceinline__ void mma_tf32(float c[4], const uint32_t a[4],
                                         const uint32_t b[2]) {
    asm volatile(
        "mma.sync.aligned.m16n8k8.row.col.f32.tf32.tf32.f32 "
        "{%0,%1,%2,%3}, {%4,%5,%6,%7}, {%8,%9}, {%0,%1,%2,%3};"
        : "+f"(c[0]), "+f"(c[1]), "+f"(c[2]), "+f"(c[3])
        : "r"(a[0]), "r"(a[1]), "r"(a[2]), "r"(a[3]), "r"(b[0]), "r"(b[1]));
}

__device__ __forceinline__ void ldsm4(uint32_t r[4], uint32_t addr) {
    asm volatile("ldmatrix.sync.aligned.m8n8.x4.shared.b16 {%0,%1,%2,%3}, [%4];"
                 : "=r"(r[0]), "=r"(r[1]), "=r"(r[2]), "=r"(r[3]) : "r"(addr));
}

__global__ void __launch_bounds__(NTHREADS, 1)
lora_gemm_kernel(const float* __restrict__ x, const uint32_t* __restrict__ Weff,
                 const float* __restrict__ bias, float* __restrict__ out,
                 int KITERS) {
    extern __shared__ float smem[];
    uint32_t smem_u32;
    asm("{ .reg .u64 t; cvta.to.shared.u64 t, %1; cvt.u32.u64 %0, t; }"
        : "=r"(smem_u32) : "l"(smem));

    const int tid = threadIdx.x;
    const int wid = tid >> 5;
    const int lid = tid & 31;
    const int gid = lid >> 2;    // 0..7
    const int qid = lid & 3;     // 0..3

    const int n0 = blockIdx.x * TILE_N;
    const int m0 = blockIdx.y * TILE_M;

    const int wm0 = (wid & 1) * 64;       // warp M offset   (2 warps over M)
    const int wn0 = (wid >> 1) * 32;      // warp N offset   (8 warps over N)

    // ---- ldmatrix per-lane addresses ----
    const int a_row  = wm0 + (lid & 15);
    const int a_koff = (lid >> 4) * 4;
    const int b_row  = wn0 + (lid & 7) + ((lid >> 4) * 8);
    const int b_koff = ((lid >> 3) & 1) * 4;

    const float* gA = x + (size_t)m0 * KDIM;
    const float* gB = (const float*)Weff + (size_t)n0 * KDIM;

    // ---- cp.async plan: A=1024 chunks, B=2048 chunks, 16B each ----
    auto issue_stage = [&](int kc, int slot) {
        uint32_t sA = smem_u32 + slot * STAGE_FLOATS * 4;
        uint32_t sB = sA + A_TILE_FLOATS * 4;
        const float* srcA = gA + kc * KC;
        const float* srcB = gB + kc * KC;
#pragma unroll
        for (int c = 0; c < 2; c++) {
            int id = tid + c * NTHREADS;        // 0..1023 : A
            int row = id >> 3, c4 = id & 7;
            cp16(sA + (row * LDS_STRIDE + c4 * 4) * 4,
                 srcA + (size_t)row * KDIM + c4 * 4);
        }
#pragma unroll
        for (int c = 0; c < 4; c++) {
            int id = tid + c * NTHREADS;        // 0..2047 : B
            int row = id >> 3, c4 = id & 7;
            cp16(sB + (row * LDS_STRIDE + c4 * 4) * 4,
                 srcB + (size_t)row * KDIM + c4 * 4);
        }
    };

    float acc[4][4][4];
#pragma unroll
    for (int i = 0; i < 4; i++)
#pragma unroll
        for (int j = 0; j < 4; j++)
#pragma unroll
            for (int e = 0; e < 4; e++) acc[i][j][e] = 0.0f;

    issue_stage(0, 0); CP_COMMIT();
    issue_stage(1, 1); CP_COMMIT();

    int cs = 0;                 // consumer slot
    int ps = 2;                 // producer slot

#pragma unroll 1
    for (int kc = 0; kc < KITERS; kc++) {
        CP_WAIT(1);
        __syncthreads();

        int nxt = kc + NSTAGES - 1;
        if (nxt < KITERS) issue_stage(nxt, ps);
        CP_COMMIT();
        if (++ps == NSTAGES) ps = 0;

        uint32_t sA = smem_u32 + cs * STAGE_FLOATS * 4;
        uint32_t sB = sA + A_TILE_FLOATS * 4;
        if (++cs == NSTAGES) cs = 0;

#pragma unroll
        for (int k8 = 0; k8 < 4; k8++) {
            const int kb = k8 * 8;
            uint32_t af[4][4], bf[4][2];
#pragma unroll
            for (int i = 0; i < 4; i++)
                ldsm4(af[i], sA + ((a_row + i * 16) * LDS_STRIDE + kb + a_koff) * 4);
#pragma unroll
            for (int p = 0; p < 2; p++) {
                uint32_t t[4];
                ldsm4(t, sB + ((b_row + p * 16) * LDS_STRIDE + kb + b_koff) * 4);
                bf[2 * p][0]     = t[0];
                bf[2 * p][1]     = t[1];
                bf[2 * p + 1][0] = t[2];
                bf[2 * p + 1][1] = t[3];
            }
#pragma unroll
            for (int i = 0; i < 4; i++)
#pragma unroll
                for (int j = 0; j < 4; j++)
                    mma_tf32(acc[i][j], af[i], bf[j]);
        }
    }

    // --- epilogue: acc + bias -> out ---
#pragma unroll
    for (int j = 0; j < 4; j++) {
        int col = n0 + wn0 + j * 8 + qid * 2;
        float2 bb = *(const float2*)(bias + col);
#pragma unroll
        for (int i = 0; i < 4; i++) {
            int row = m0 + wm0 + i * 16 + gid;
            float2 v0 = make_float2(acc[i][j][0] + bb.x, acc[i][j][1] + bb.y);
            float2 v1 = make_float2(acc[i][j][2] + bb.x, acc[i][j][3] + bb.y);
            *(float2*)(out + (size_t)row * MDIM + col) = v0;
            *(float2*)(out + (size_t)(row + 8) * MDIM + col) = v1;
        }
    }
}

// ============================================================================
// Host launch
// ============================================================================
extern "C" void kernel_launch(void* const* d_in, const int* in_sizes, int n_in,
                              void* d_out, int out_size) {
    const float* x = (const float*)d_in[0];
    const float* W = (const float*)d_in[1];
    const float* b = (const float*)d_in[2];
    const float* A = (const float*)d_in[3];
    const float* B = (const float*)d_in[4];
    float* out = (float*)d_out;
    int T = in_sizes[0] / KDIM;

    void* weff_ptr = nullptr;
    cudaGetSymbolAddress(&weff_ptr, g_Weff);

    int quads = (MDIM * KDIM) / 4;
    weff_prep_kernel<<<quads / 256, 256>>>(W, A, B, (uint32_t*)weff_ptr);

    cudaFuncSetAttribute(lora_gemm_kernel,
                         cudaFuncAttributeMaxDynamicSharedMemorySize, SMEM_BYTES);

    dim3 grid(MDIM / TILE_N, T / TILE_M);   // (16, 64) — n fastest for L2 reuse
    lora_gemm_kernel<<<grid, NTHREADS, SMEM_BYTES>>>(
        x, (const uint32_t*)weff_ptr, b, out, KDIM / KC);
}

// round 5
// speedup vs baseline: 1.2593x; 1.0260x over previous
#include <cuda_runtime.h>
#include <cuda.h>
#include <cstdint>

// ============================================================================
// LoRALinear: out[T,4096] = x[T,4096] @ (W + a*A@B^T)^T + b
// sm_103 baseline ISA (no tcgen05):
//   kernel 1: Weff = rna_tf32(W + alpha*A@B^T)
//   kernel 2: tf32 mma.sync GEMM, cp.async 3-stage pipeline, ldmatrix frags,
//             256 threads/CTA, 2 CTAs/SM (independent barrier domains overlap)
// ============================================================================
#define KDIM 4096
#define MDIM 4096
#define RANK 8
#define LORA_ALPHA (8.0f / RANK)

#define TILE_M 128
#define TILE_N 128
#define KC 32
#define NSTAGES 3
#define NTHREADS 256
#define LDS_STRIDE 36                       // 32 + 4 pad floats

#define A_TILE_FLOATS (TILE_M * LDS_STRIDE) // 4608
#define B_TILE_FLOATS (TILE_N * LDS_STRIDE) // 4608
#define STAGE_FLOATS  (A_TILE_FLOATS + B_TILE_FLOATS)   // 9216
#define SMEM_BYTES    (NSTAGES * STAGE_FLOATS * 4)      // 110592 per CTA

__device__ float g_Weff[(size_t)MDIM * (size_t)KDIM];

// ============================================================================
// Kernel 1: Weff = rna_tf32(W + alpha * A @ B^T)
// ============================================================================
__device__ __forceinline__ uint32_t f2tf32(float f) {
    uint32_t o;
    asm("cvt.rna.tf32.f32 %0, %1;" : "=r"(o) : "f"(f));
    return o;
}

__global__ void __launch_bounds__(256)
weff_prep_kernel(const float* __restrict__ W, const float* __restrict__ A,
                 const float* __restrict__ Bm, uint32_t* __restrict__ Weff) {
    int i = blockIdx.x * blockDim.x + threadIdx.x;   // float4 index
    int m  = i >> 10;
    int kq = i & 1023;
    const float4* Arow = (const float4*)(A + (size_t)m * RANK);
    float4 a0 = Arow[0], a1 = Arow[1];
    float4 w = ((const float4*)W)[i];
    float r[4];
#pragma unroll
    for (int j = 0; j < 4; j++) {
        const float4* Brow = (const float4*)(Bm + (size_t)(kq * 4 + j) * RANK);
        float4 b0 = Brow[0], b1 = Brow[1];
        r[j] = a0.x * b0.x + a0.y * b0.y + a0.z * b0.z + a0.w * b0.w
             + a1.x * b1.x + a1.y * b1.y + a1.z * b1.z + a1.w * b1.w;
    }
    uint4 o;
    o.x = f2tf32(w.x + LORA_ALPHA * r[0]);
    o.y = f2tf32(w.y + LORA_ALPHA * r[1]);
    o.z = f2tf32(w.z + LORA_ALPHA * r[2]);
    o.w = f2tf32(w.w + LORA_ALPHA * r[3]);
    ((uint4*)Weff)[i] = o;
}

// ============================================================================
// Kernel 2: C = x @ Weff^T + b
// ============================================================================
__device__ __forceinline__ void cp16(uint32_t dst_smem, const void* src) {
    asm volatile("cp.async.cg.shared.global [%0], [%1], 16;"
                 :: "r"(dst_smem), "l"(src) : "memory");
}
#define CP_COMMIT() asm volatile("cp.async.commit_group;" ::: "memory")
#define CP_WAIT(n)  asm volatile("cp.async.wait_group %0;" :: "n"(n) : "memory")

__device__ __forceinline__ void mma_tf32(float c[4], const uint32_t a[4],
                                         const uint32_t b[2]) {
    asm volatile(
        "mma.sync.aligned.m16n8k8.row.col.f32.tf32.tf32.f32 "
        "{%0,%1,%2,%3}, {%4,%5,%6,%7}, {%8,%9}, {%0,%1,%2,%3};"
        : "+f"(c[0]), "+f"(c[1]), "+f"(c[2]), "+f"(c[3])
        : "r"(a[0]), "r"(a[1]), "r"(a[2]), "r"(a[3]), "r"(b[0]), "r"(b[1]));
}

__device__ __forceinline__ void ldsm4(uint32_t r[4], uint32_t addr) {
    asm volatile("ldmatrix.sync.aligned.m8n8.x4.shared.b16 {%0,%1,%2,%3}, [%4];"
                 : "=r"(r[0]), "=r"(r[1]), "=r"(r[2]), "=r"(r[3]) : "r"(addr));
}

__global__ void __launch_bounds__(NTHREADS, 2)
lora_gemm_kernel(const float* __restrict__ x, const uint32_t* __restrict__ Weff,
                 const float* __restrict__ bias, float* __restrict__ out,
                 int KITERS) {
    extern __shared__ float smem[];
    uint32_t smem_u32;
    asm("{ .reg .u64 t; cvta.to.shared.u64 t, %1; cvt.u32.u64 %0, t; }"
        : "=r"(smem_u32) : "l"(smem));

    const int tid = threadIdx.x;
    const int wid = tid >> 5;
    const int lid = tid & 31;
    const int gid = lid >> 2;    // 0..7
    const int qid = lid & 3;     // 0..3

    const int n0 = blockIdx.x * TILE_N;
    const int m0 = blockIdx.y * TILE_M;

    const int wm0 = (wid & 1) * 64;       // warp M offset (2 warps over M)
    const int wn0 = (wid >> 1) * 32;      // warp N offset (4 warps over N)

    // ---- ldmatrix per-lane addresses ----
    const int a_row  = wm0 + (lid & 15);
    const int a_koff = (lid >> 4) * 4;
    const int b_row  = wn0 + (lid & 7) + ((lid >> 4) * 8);
    const int b_koff = ((lid >> 3) & 1) * 4;

    const float* gA = x + (size_t)m0 * KDIM;
    const float* gB = (const float*)Weff + (size_t)n0 * KDIM;

    // ---- cp.async plan: A=1024 chunks, B=1024 chunks, 16B each ----
    auto issue_stage = [&](int kc, int slot) {
        uint32_t sA = smem_u32 + slot * STAGE_FLOATS * 4;
        uint32_t sB = sA + A_TILE_FLOATS * 4;
        const float* srcA = gA + kc * KC;
        const float* srcB = gB + kc * KC;
#pragma unroll
        for (int c = 0; c < 4; c++) {
            int id = tid + c * NTHREADS;        // 0..1023 : A
            int row = id >> 3, c4 = id & 7;
            cp16(sA + (row * LDS_STRIDE + c4 * 4) * 4,
                 srcA + (size_t)row * KDIM + c4 * 4);
        }
#pragma unroll
        for (int c = 0; c < 4; c++) {
            int id = tid + c * NTHREADS;        // 0..1023 : B
            int row = id >> 3, c4 = id & 7;
            cp16(sB + (row * LDS_STRIDE + c4 * 4) * 4,
                 srcB + (size_t)row * KDIM + c4 * 4);
        }
    };

    float acc[4][4][4];
#pragma unroll
    for (int i = 0; i < 4; i++)
#pragma unroll
        for (int j = 0; j < 4; j++)
#pragma unroll
            for (int e = 0; e < 4; e++) acc[i][j][e] = 0.0f;

    issue_stage(0, 0); CP_COMMIT();
    issue_stage(1, 1); CP_COMMIT();

    int cs = 0;                 // consumer slot
    int ps = 2;                 // producer slot

#pragma unroll 1
    for (int kc = 0; kc < KITERS; kc++) {
        CP_WAIT(1);
        __syncthreads();

        int nxt = kc + NSTAGES - 1;
        if (nxt < KITERS) issue_stage(nxt, ps);
        CP_COMMIT();
        if (++ps == NSTAGES) ps = 0;

        uint32_t sA = smem_u32 + cs * STAGE_FLOATS * 4;
        uint32_t sB = sA + A_TILE_FLOATS * 4;
        if (++cs == NSTAGES) cs = 0;

#pragma unroll
        for (int k8 = 0; k8 < 4; k8++) {
            const int kb = k8 * 8;
            uint32_t af[4][4], bf[4][2];
#pragma unroll
            for (int i = 0; i < 4; i++)
                ldsm4(af[i], sA + ((a_row + i * 16) * LDS_STRIDE + kb + a_koff) * 4);
#pragma unroll
            for (int p = 0; p < 2; p++) {
                uint32_t t[4];
                ldsm4(t, sB + ((b_row + p * 16) * LDS_STRIDE + kb + b_koff) * 4);
                bf[2 * p][0]     = t[0];
                bf[2 * p][1]     = t[1];
                bf[2 * p + 1][0] = t[2];
                bf[2 * p + 1][1] = t[3];
            }
#pragma unroll
            for (int i = 0; i < 4; i++)
#pragma unroll
                for (int j = 0; j < 4; j++)
                    mma_tf32(acc[i][j], af[i], bf[j]);
        }
    }

    // --- epilogue: acc + bias -> out ---
#pragma unroll
    for (int j = 0; j < 4; j++) {
        int col = n0 + wn0 + j * 8 + qid * 2;
        float2 bb = *(const float2*)(bias + col);
#pragma unroll
        for (int i = 0; i < 4; i++) {
            int row = m0 + wm0 + i * 16 + gid;
            float2 v0 = make_float2(acc[i][j][0] + bb.x, acc[i][j][1] + bb.y);
            float2 v1 = make_float2(acc[i][j][2] + bb.x, acc[i][j][3] + bb.y);
            *(float2*)(out + (size_t)row * MDIM + col) = v0;
            *(float2*)(out + (size_t)(row + 8) * MDIM + col) = v1;
        }
    }
}

// ============================================================================
// Host launch
// ============================================================================
extern "C" void kernel_launch(void* const* d_in, const int* in_sizes, int n_in,
                              void* d_out, int out_size) {
    const float* x = (const float*)d_in[0];
    const float* W = (const float*)d_in[1];
    const float* b = (const float*)d_in[2];
    const float* A = (const float*)d_in[3];
    const float* B = (const float*)d_in[4];
    float* out = (float*)d_out;
    int T = in_sizes[0] / KDIM;

    void* weff_ptr = nullptr;
    cudaGetSymbolAddress(&weff_ptr, g_Weff);

    int quads = (MDIM * KDIM) / 4;
    weff_prep_kernel<<<quads / 256, 256>>>(W, A, B, (uint32_t*)weff_ptr);

    cudaFuncSetAttribute(lora_gemm_kernel,
                         cudaFuncAttributeMaxDynamicSharedMemorySize, SMEM_BYTES);

    dim3 grid(MDIM / TILE_N, T / TILE_M);   // (32, 64) — n fastest for L2 reuse
    lora_gemm_kernel<<<grid, NTHREADS, SMEM_BYTES>>>(
        x, (const uint32_t*)weff_ptr, b, out, KDIM / KC);
}

// round 6
// speedup vs baseline: 1.6966x; 1.3472x over previous
#include <cuda_runtime.h>
#include <cuda.h>
#include <cstdint>

// ============================================================================
// LoRALinear: out[T,4096] = x[T,4096] @ (W + a*A@B^T)^T + b
// sm_103 baseline ISA (no tcgen05, but TMA/mbarrier = sm_90 baseline OK):
//   kernel 1: Weff = rna_tf32(W + alpha*A@B^T)
//   kernel 2: tf32 mma.sync GEMM; TMA bulk-tensor loads into SW128 smem,
//             full/empty mbarrier pipeline (no cp.async, no per-kc syncthreads),
//             256 thr/CTA, 2 CTAs/SM
// ============================================================================
#define KDIM 4096
#define MDIM 4096
#define RANK 8
#define LORA_ALPHA (8.0f / RANK)

#define TILE_M 128
#define TILE_N 128
#define KC 32                 // 32 floats = 128 bytes = one SW128 row
#define NSTAGES 3
#define NTHREADS 256
#define KITERS (KDIM / KC)    // 128

#define A_TILE_BYTES (TILE_M * 128)            // 16384
#define B_TILE_BYTES (TILE_N * 128)            // 16384
#define STAGE_BYTES  (A_TILE_BYTES + B_TILE_BYTES)   // 32768

// SMEM layout: [0..48) full mbarriers, [64..112) empty mbarriers, tiles @1024
#define SMEM_FULL(s)  ((s) * 16)
#define SMEM_EMPTY(s) (64 + (s) * 16)
#define SMEM_TILES    1024
#define SMEM_A(s) (SMEM_TILES + (s) * STAGE_BYTES)
#define SMEM_B(s) (SMEM_A(s) + A_TILE_BYTES)
#define SMEM_BYTES (SMEM_TILES + NSTAGES * STAGE_BYTES)   // 99328

__device__ float g_Weff[(size_t)MDIM * (size_t)KDIM];

// ============================================================================
// PTX helpers
// ============================================================================
#define MBARRIER_INIT(mbar, count) \
    asm volatile("mbarrier.init.shared.b64 [%0], %1;" \
                 :: "r"((uint32_t)(mbar)), "r"((uint32_t)(count)) : "memory")

#define MBARRIER_ARRIVE(mbar) \
    asm volatile("mbarrier.arrive.shared.b64 _, [%0];" \
                 :: "r"((uint32_t)(mbar)) : "memory")

#define MBARRIER_EXPECT_TX(mbar, tx_bytes) \
    asm volatile("mbarrier.arrive.expect_tx.shared.b64 _, [%0], %1;" \
                 :: "r"((uint32_t)(mbar)), "r"((uint32_t)(tx_bytes)) : "memory")

#define MBARRIER_WAIT_PARITY(mbar, phase_parity) do { \
    uint32_t _mbar = (uint32_t)(mbar); \
    uint32_t _parity = (uint32_t)(phase_parity); \
    uint32_t _done; \
    asm volatile( \
        "{\n\t" \
        ".reg .pred p;\n\t" \
        "mbarrier.try_wait.parity.acquire.cta.shared::cta.b64 p, [%1], %2;\n\t" \
        "selp.b32 %0, 1, 0, p;\n\t" \
        "}" \
        : "=r"(_done) : "r"(_mbar), "r"(_parity) : "memory"); \
    if (!_done) { \
        asm volatile( \
            "{\n\t" \
            ".reg .pred P1;\n\t" \
            "WAIT_LOOP_%=:\n\t" \
            "mbarrier.try_wait.parity.acquire.cta.shared::cta.b64 P1, [%0], %1, 0x989680;\n\t" \
            "@P1 bra.uni WAIT_DONE_%=;\n\t" \
            "bra.uni WAIT_LOOP_%=;\n\t" \
            "WAIT_DONE_%=:\n\t" \
            "}" \
            :: "r"(_mbar), "r"(_parity) : "memory"); \
    } \
} while(0)

__device__ __forceinline__ void tma_load_2d(
    uint32_t smem_addr, const void* tensor_map,
    int32_t cx, int32_t cy, uint32_t mbar
) {
    asm volatile(
        "cp.async.bulk.tensor.2d.shared::cta.global.tile.mbarrier::complete_tx::bytes "
        "[%0], [%1, {%2, %3}], [%4];"
        :: "r"(smem_addr), "l"(tensor_map), "r"(cx), "r"(cy), "r"(mbar)
        : "memory");
}

__device__ __forceinline__ void mma_tf32(float c[4], const uint32_t a[4],
                                         const uint32_t b[2]) {
    asm volatile(
        "mma.sync.aligned.m16n8k8.row.col.f32.tf32.tf32.f32 "
        "{%0,%1,%2,%3}, {%4,%5,%6,%7}, {%8,%9}, {%0,%1,%2,%3};"
        : "+f"(c[0]), "+f"(c[1]), "+f"(c[2]), "+f"(c[3])
        : "r"(a[0]), "r"(a[1]), "r"(a[2]), "r"(a[3]), "r"(b[0]), "r"(b[1]));
}

__device__ __forceinline__ void ldsm4(uint32_t r[4], uint32_t addr) {
    asm volatile("ldmatrix.sync.aligned.m8n8.x4.shared.b16 {%0,%1,%2,%3}, [%4];"
                 : "=r"(r[0]), "=r"(r[1]), "=r"(r[2]), "=r"(r[3]) : "r"(addr));
}

// ============================================================================
// Kernel 1: Weff = rna_tf32(W + alpha * A @ B^T)
// ============================================================================
__device__ __forceinline__ uint32_t f2tf32(float f) {
    uint32_t o;
    asm("cvt.rna.tf32.f32 %0, %1;" : "=r"(o) : "f"(f));
    return o;
}

__global__ void __launch_bounds__(256)
weff_prep_kernel(const float* __restrict__ W, const float* __restrict__ A,
                 const float* __restrict__ Bm, uint32_t* __restrict__ Weff) {
    int i = blockIdx.x * blockDim.x + threadIdx.x;   // float4 index
    int m  = i >> 10;
    int kq = i & 1023;
    const float4* Arow = (const float4*)(A + (size_t)m * RANK);
    float4 a0 = Arow[0], a1 = Arow[1];
    float4 w = ((const float4*)W)[i];
    float r[4];
#pragma unroll
    for (int j = 0; j < 4; j++) {
        const float4* Brow = (const float4*)(Bm + (size_t)(kq * 4 + j) * RANK);
        float4 b0 = Brow[0], b1 = Brow[1];
        r[j] = a0.x * b0.x + a0.y * b0.y + a0.z * b0.z + a0.w * b0.w
             + a1.x * b1.x + a1.y * b1.y + a1.z * b1.z + a1.w * b1.w;
    }
    uint4 o;
    o.x = f2tf32(w.x + LORA_ALPHA * r[0]);
    o.y = f2tf32(w.y + LORA_ALPHA * r[1]);
    o.z = f2tf32(w.z + LORA_ALPHA * r[2]);
    o.w = f2tf32(w.w + LORA_ALPHA * r[3]);
    ((uint4*)Weff)[i] = o;
}

// ============================================================================
// Kernel 2: C = x @ Weff^T + b
// ============================================================================
__global__ void __launch_bounds__(NTHREADS, 2)
lora_gemm_kernel(const __grid_constant__ CUtensorMap tmx,
                 const __grid_constant__ CUtensorMap tmw,
                 const float* __restrict__ bias, float* __restrict__ out) {
    extern __shared__ __align__(1024) char smem[];
    uint32_t sb;
    asm("{ .reg .u64 t; cvta.to.shared.u64 t, %1; cvt.u32.u64 %0, t; }"
        : "=r"(sb) : "l"(smem));

    const int tid = threadIdx.x;
    const int wid = tid >> 5;
    const int lid = tid & 31;
    const int gid = lid >> 2;
    const int qid = lid & 3;

    const int n0 = blockIdx.x * TILE_N;
    const int m0 = blockIdx.y * TILE_M;

    const int wm0 = (wid & 1) * 64;       // 2 warps over M
    const int wn0 = (wid >> 1) * 32;      // 4 warps over N

    // ldmatrix lane geometry (SW128 swizzled rows, 128 B/row)
    const int a_row  = wm0 + (lid & 15);
    const int a_k4   = (lid >> 4) * 16;                    // byte col offset
    const uint32_t a_swz = (uint32_t)((a_row & 7) << 4);
    const int b_row  = wn0 + (lid & 7) + ((lid >> 4) * 8);
    const int b_k4   = ((lid >> 3) & 1) * 16;
    const uint32_t b_swz = (uint32_t)((b_row & 7) << 4);

    if (tid == 0) {
        for (int s = 0; s < NSTAGES; s++) {
            MBARRIER_INIT(sb + SMEM_FULL(s), 1);
            MBARRIER_INIT(sb + SMEM_EMPTY(s), 8);
        }
    }
    __syncthreads();

    // prologue: produce stages kc=0,1 (slots 0,1) — no empty wait needed
    if (tid == 0) {
#pragma unroll
        for (int p = 0; p < 2; p++) {
            MBARRIER_EXPECT_TX(sb + SMEM_FULL(p), STAGE_BYTES);
            tma_load_2d(sb + SMEM_A(p), &tmx, p * KC, m0, sb + SMEM_FULL(p));
            tma_load_2d(sb + SMEM_B(p), &tmw, p * KC, n0, sb + SMEM_FULL(p));
        }
    }

    float acc[4][4][4];
#pragma unroll
    for (int i = 0; i < 4; i++)
#pragma unroll
        for (int j = 0; j < 4; j++)
#pragma unroll
            for (int e = 0; e < 4; e++) acc[i][j][e] = 0.0f;

    int cs = 0, cph = 0;        // consumer slot/phase
    int ps = 2, pph = 1;        // producer slot/phase (phase 1: first waits pass)

#pragma unroll 1
    for (int kc = 0; kc < KITERS; kc++) {
        // producer: thread 0 issues stage kc+2 into slot ps
        if (tid == 0 && kc + 2 < KITERS) {
            MBARRIER_WAIT_PARITY(sb + SMEM_EMPTY(ps), pph);
            MBARRIER_EXPECT_TX(sb + SMEM_FULL(ps), STAGE_BYTES);
            tma_load_2d(sb + SMEM_A(ps), &tmx, (kc + 2) * KC, m0, sb + SMEM_FULL(ps));
            tma_load_2d(sb + SMEM_B(ps), &tmw, (kc + 2) * KC, n0, sb + SMEM_FULL(ps));
            if (++ps == NSTAGES) { ps = 0; pph ^= 1; }
        }

        // consumer: wait for stage, compute
        MBARRIER_WAIT_PARITY(sb + SMEM_FULL(cs), cph);
        uint32_t sA = sb + SMEM_A(cs);
        uint32_t sB = sb + SMEM_B(cs);

#pragma unroll
        for (int k8 = 0; k8 < 4; k8++) {
            const uint32_t kb4 = k8 * 32;          // byte col of this k8 chunk
            uint32_t af[4][4], bf[4][2];
            const uint32_t ca = (kb4 + a_k4) ^ a_swz;
            const uint32_t cb = (kb4 + b_k4) ^ b_swz;
#pragma unroll
            for (int i = 0; i < 4; i++)
                ldsm4(af[i], sA + (a_row + i * 16) * 128 + ca);
#pragma unroll
            for (int p = 0; p < 2; p++) {
                uint32_t t[4];
                ldsm4(t, sB + (b_row + p * 16) * 128 + cb);
                bf[2 * p][0]     = t[0];
                bf[2 * p][1]     = t[1];
                bf[2 * p + 1][0] = t[2];
                bf[2 * p + 1][1] = t[3];
            }
#pragma unroll
            for (int i = 0; i < 4; i++)
#pragma unroll
                for (int j = 0; j < 4; j++)
                    mma_tf32(acc[i][j], af[i], bf[j]);
        }

        if (lid == 0) MBARRIER_ARRIVE(sb + SMEM_EMPTY(cs));
        if (++cs == NSTAGES) { cs = 0; cph ^= 1; }
    }

    // --- epilogue: acc + bias -> out ---
#pragma unroll
    for (int j = 0; j < 4; j++) {
        int col = n0 + wn0 + j * 8 + qid * 2;
        float2 bb = *(const float2*)(bias + col);
#pragma unroll
        for (int i = 0; i < 4; i++) {
            int row = m0 + wm0 + i * 16 + gid;
            float2 v0 = make_float2(acc[i][j][0] + bb.x, acc[i][j][1] + bb.y);
            float2 v1 = make_float2(acc[i][j][2] + bb.x, acc[i][j][3] + bb.y);
            *(float2*)(out + (size_t)row * MDIM + col) = v0;
            *(float2*)(out + (size_t)(row + 8) * MDIM + col) = v1;
        }
    }
}

// ============================================================================
// Host launch
// ============================================================================
typedef CUresult (*EncodeTiledFn)(
    CUtensorMap*, CUtensorMapDataType, cuuint32_t, void*,
    const cuuint64_t*, const cuuint64_t*, const cuuint32_t*, const cuuint32_t*,
    CUtensorMapInterleave, CUtensorMapSwizzle, CUtensorMapL2promotion,
    CUtensorMapFloatOOBfill);

static void make_map_2d(CUtensorMap* tm, const void* ptr,
                        unsigned long long d0, unsigned long long d1) {
    EncodeTiledFn fn = nullptr;
    cudaDriverEntryPointQueryResult qr;
    cudaGetDriverEntryPoint("cuTensorMapEncodeTiled", (void**)&fn,
                            cudaEnableDefault, &qr);
    cuuint64_t dims[2]    = {d0, d1};
    cuuint64_t strides[1] = {d0 * sizeof(float)};
    cuuint32_t box[2]     = {KC, TILE_M};     // 32 floats = 128B x 128 rows
    cuuint32_t es[2]      = {1, 1};
    fn(tm, CU_TENSOR_MAP_DATA_TYPE_FLOAT32, 2, (void*)ptr, dims, strides, box, es,
       CU_TENSOR_MAP_INTERLEAVE_NONE, CU_TENSOR_MAP_SWIZZLE_128B,
       CU_TENSOR_MAP_L2_PROMOTION_L2_128B, CU_TENSOR_MAP_FLOAT_OOB_FILL_NONE);
}

extern "C" void kernel_launch(void* const* d_in, const int* in_sizes, int n_in,
                              void* d_out, int out_size) {
    const float* x = (const float*)d_in[0];
    const float* W = (const float*)d_in[1];
    const float* b = (const float*)d_in[2];
    const float* A = (const float*)d_in[3];
    const float* B = (const float*)d_in[4];
    float* out = (float*)d_out;
    int T = in_sizes[0] / KDIM;

    void* weff_ptr = nullptr;
    cudaGetSymbolAddress(&weff_ptr, g_Weff);

    int quads = (MDIM * KDIM) / 4;
    weff_prep_kernel<<<quads / 256, 256>>>(W, A, B, (uint32_t*)weff_ptr);

    CUtensorMap tmx, tmw;
    make_map_2d(&tmx, x, KDIM, (unsigned long long)T);
    make_map_2d(&tmw, weff_ptr, KDIM, MDIM);

    cudaFuncSetAttribute(lora_gemm_kernel,
                         cudaFuncAttributeMaxDynamicSharedMemorySize, SMEM_BYTES);

    dim3 grid(MDIM / TILE_N, T / TILE_M);   // (32, 64) — n fastest for L2 reuse
    lora_gemm_kernel<<<grid, NTHREADS, SMEM_BYTES>>>(tmx, tmw, b, out);
}

// round 7
// speedup vs baseline: 1.8568x; 1.0944x over previous
#include <cuda_runtime.h>
#include <cuda.h>
#include <cstdint>

// ============================================================================
// LoRALinear: out[T,4096] = x[T,4096] @ (W + a*A@B^T)^T + b
// sm_103 baseline ISA (no tcgen05, but TMA/mbarrier = sm_90 baseline OK):
//   kernel 1: Weff = rna_tf32(W + alpha*A@B^T)  -- tiled: B rows in registers,
//             A staged in smem, pure 128MB stream (R7: was 9 loads/quad)
//   kernel 2: tf32 mma.sync GEMM; TMA loads into SW128 smem, full/empty
//             mbarrier pipeline, 256 thr/CTA, 2 CTAs/SM  (unchanged from R6)
// ============================================================================
#define KDIM 4096
#define MDIM 4096
#define RANK 8
#define LORA_ALPHA (8.0f / RANK)

#define TILE_M 128
#define TILE_N 128
#define KC 32                 // 32 floats = 128 bytes = one SW128 row
#define NSTAGES 3
#define NTHREADS 256
#define KITERS (KDIM / KC)    // 128

#define A_TILE_BYTES (TILE_M * 128)            // 16384
#define B_TILE_BYTES (TILE_N * 128)            // 16384
#define STAGE_BYTES  (A_TILE_BYTES + B_TILE_BYTES)   // 32768

#define SMEM_FULL(s)  ((s) * 16)
#define SMEM_EMPTY(s) (64 + (s) * 16)
#define SMEM_TILES    1024
#define SMEM_A(s) (SMEM_TILES + (s) * STAGE_BYTES)
#define SMEM_B(s) (SMEM_A(s) + A_TILE_BYTES)
#define SMEM_BYTES (SMEM_TILES + NSTAGES * STAGE_BYTES)   // 99328

// prep tiling
#define PREP_MT 32            // m rows per block
#define PREP_KT 1024          // k cols per block (= 256 quads = 256 threads)

__device__ float g_Weff[(size_t)MDIM * (size_t)KDIM];

// ============================================================================
// PTX helpers
// ============================================================================
#define MBARRIER_INIT(mbar, count) \
    asm volatile("mbarrier.init.shared.b64 [%0], %1;" \
                 :: "r"((uint32_t)(mbar)), "r"((uint32_t)(count)) : "memory")

#define MBARRIER_ARRIVE(mbar) \
    asm volatile("mbarrier.arrive.shared.b64 _, [%0];" \
                 :: "r"((uint32_t)(mbar)) : "memory")

#define MBARRIER_EXPECT_TX(mbar, tx_bytes) \
    asm volatile("mbarrier.arrive.expect_tx.shared.b64 _, [%0], %1;" \
                 :: "r"((uint32_t)(mbar)), "r"((uint32_t)(tx_bytes)) : "memory")

#define MBARRIER_WAIT_PARITY(mbar, phase_parity) do { \
    uint32_t _mbar = (uint32_t)(mbar); \
    uint32_t _parity = (uint32_t)(phase_parity); \
    uint32_t _done; \
    asm volatile( \
        "{\n\t" \
        ".reg .pred p;\n\t" \
        "mbarrier.try_wait.parity.acquire.cta.shared::cta.b64 p, [%1], %2;\n\t" \
        "selp.b32 %0, 1, 0, p;\n\t" \
        "}" \
        : "=r"(_done) : "r"(_mbar), "r"(_parity) : "memory"); \
    if (!_done) { \
        asm volatile( \
            "{\n\t" \
            ".reg .pred P1;\n\t" \
            "WAIT_LOOP_%=:\n\t" \
            "mbarrier.try_wait.parity.acquire.cta.shared::cta.b64 P1, [%0], %1, 0x989680;\n\t" \
            "@P1 bra.uni WAIT_DONE_%=;\n\t" \
            "bra.uni WAIT_LOOP_%=;\n\t" \
            "WAIT_DONE_%=:\n\t" \
            "}" \
            :: "r"(_mbar), "r"(_parity) : "memory"); \
    } \
} while(0)

__device__ __forceinline__ void tma_load_2d(
    uint32_t smem_addr, const void* tensor_map,
    int32_t cx, int32_t cy, uint32_t mbar
) {
    asm volatile(
        "cp.async.bulk.tensor.2d.shared::cta.global.tile.mbarrier::complete_tx::bytes "
        "[%0], [%1, {%2, %3}], [%4];"
        :: "r"(smem_addr), "l"(tensor_map), "r"(cx), "r"(cy), "r"(mbar)
        : "memory");
}

__device__ __forceinline__ void mma_tf32(float c[4], const uint32_t a[4],
                                         const uint32_t b[2]) {
    asm volatile(
        "mma.sync.aligned.m16n8k8.row.col.f32.tf32.tf32.f32 "
        "{%0,%1,%2,%3}, {%4,%5,%6,%7}, {%8,%9}, {%0,%1,%2,%3};"
        : "+f"(c[0]), "+f"(c[1]), "+f"(c[2]), "+f"(c[3])
        : "r"(a[0]), "r"(a[1]), "r"(a[2]), "r"(a[3]), "r"(b[0]), "r"(b[1]));
}

__device__ __forceinline__ void ldsm4(uint32_t r[4], uint32_t addr) {
    asm volatile("ldmatrix.sync.aligned.m8n8.x4.shared.b16 {%0,%1,%2,%3}, [%4];"
                 : "=r"(r[0]), "=r"(r[1]), "=r"(r[2]), "=r"(r[3]) : "r"(addr));
}

__device__ __forceinline__ uint32_t f2tf32(float f) {
    uint32_t o;
    asm("cvt.rna.tf32.f32 %0, %1;" : "=r"(o) : "f"(f));
    return o;
}

// ============================================================================
// Kernel 1 (R7): Weff = rna_tf32(W + alpha * A @ B^T), tiled.
//   Block: PREP_MT m-rows x PREP_KT k-cols. Thread t owns quad column t
//   (k = k0 + 4t): loads its 4 B rows ONCE into registers, then streams
//   PREP_MT coalesced W-quads. A rows staged in smem (broadcast reads).
// ============================================================================
__global__ void __launch_bounds__(256)
weff_prep_kernel(const float* __restrict__ W, const float* __restrict__ A,
                 const float* __restrict__ Bm, uint32_t* __restrict__ Weff) {
    __shared__ float As[PREP_MT * RANK];           // 1 KB

    const int tid = threadIdx.x;
    const int mt = blockIdx.x / (KDIM / PREP_KT);  // m-tile
    const int kt = blockIdx.x % (KDIM / PREP_KT);  // k-tile
    const int m0 = mt * PREP_MT;
    const int k0 = kt * PREP_KT;

    // stage A rows [m0, m0+PREP_MT) -- 256 floats, one per thread
    if (tid < PREP_MT * RANK)
        As[tid] = A[(size_t)m0 * RANK + tid];
    __syncthreads();

    // this thread's 4 B rows (k = k0+4t .. k0+4t+3), kept in registers
    float4 b0[4], b1[4];
#pragma unroll
    for (int j = 0; j < 4; j++) {
        const float4* Brow = (const float4*)(Bm + (size_t)(k0 + tid * 4 + j) * RANK);
        b0[j] = Brow[0];
        b1[j] = Brow[1];
    }

    const size_t qbase = (size_t)(k0 >> 2) + tid;  // quad col index
#pragma unroll 4
    for (int q = 0; q < PREP_MT; q++) {
        const int m = m0 + q;
        const float4* Ar = (const float4*)(As + q * RANK);
        float4 a0 = Ar[0], a1 = Ar[1];
        size_t off = (size_t)m * (KDIM / 4) + qbase;
        float4 w = ((const float4*)W)[off];
        float r[4];
#pragma unroll
        for (int j = 0; j < 4; j++) {
            r[j] = a0.x * b0[j].x + a0.y * b0[j].y + a0.z * b0[j].z + a0.w * b0[j].w
                 + a1.x * b1[j].x + a1.y * b1[j].y + a1.z * b1[j].z + a1.w * b1[j].w;
        }
        uint4 o;
        o.x = f2tf32(w.x + LORA_ALPHA * r[0]);
        o.y = f2tf32(w.y + LORA_ALPHA * r[1]);
        o.z = f2tf32(w.z + LORA_ALPHA * r[2]);
        o.w = f2tf32(w.w + LORA_ALPHA * r[3]);
        ((uint4*)Weff)[off] = o;
    }
}

// ============================================================================
// Kernel 2: C = x @ Weff^T + b   (unchanged from R6)
// ============================================================================
__global__ void __launch_bounds__(NTHREADS, 2)
lora_gemm_kernel(const __grid_constant__ CUtensorMap tmx,
                 const __grid_constant__ CUtensorMap tmw,
                 const float* __restrict__ bias, float* __restrict__ out) {
    extern __shared__ __align__(1024) char smem[];
    uint32_t sb;
    asm("{ .reg .u64 t; cvta.to.shared.u64 t, %1; cvt.u32.u64 %0, t; }"
        : "=r"(sb) : "l"(smem));

    const int tid = threadIdx.x;
    const int wid = tid >> 5;
    const int lid = tid & 31;
    const int gid = lid >> 2;
    const int qid = lid & 3;

    const int n0 = blockIdx.x * TILE_N;
    const int m0 = blockIdx.y * TILE_M;

    const int wm0 = (wid & 1) * 64;       // 2 warps over M
    const int wn0 = (wid >> 1) * 32;      // 4 warps over N

    const int a_row  = wm0 + (lid & 15);
    const int a_k4   = (lid >> 4) * 16;
    const uint32_t a_swz = (uint32_t)((a_row & 7) << 4);
    const int b_row  = wn0 + (lid & 7) + ((lid >> 4) * 8);
    const int b_k4   = ((lid >> 3) & 1) * 16;
    const uint32_t b_swz = (uint32_t)((b_row & 7) << 4);

    if (tid == 0) {
        for (int s = 0; s < NSTAGES; s++) {
            MBARRIER_INIT(sb + SMEM_FULL(s), 1);
            MBARRIER_INIT(sb + SMEM_EMPTY(s), 8);
        }
    }
    __syncthreads();

    if (tid == 0) {
#pragma unroll
        for (int p = 0; p < 2; p++) {
            MBARRIER_EXPECT_TX(sb + SMEM_FULL(p), STAGE_BYTES);
            tma_load_2d(sb + SMEM_A(p), &tmx, p * KC, m0, sb + SMEM_FULL(p));
            tma_load_2d(sb + SMEM_B(p), &tmw, p * KC, n0, sb + SMEM_FULL(p));
        }
    }

    float acc[4][4][4];
#pragma unroll
    for (int i = 0; i < 4; i++)
#pragma unroll
        for (int j = 0; j < 4; j++)
#pragma unroll
            for (int e = 0; e < 4; e++) acc[i][j][e] = 0.0f;

    int cs = 0, cph = 0;
    int ps = 2, pph = 1;

#pragma unroll 1
    for (int kc = 0; kc < KITERS; kc++) {
        if (tid == 0 && kc + 2 < KITERS) {
            MBARRIER_WAIT_PARITY(sb + SMEM_EMPTY(ps), pph);
            MBARRIER_EXPECT_TX(sb + SMEM_FULL(ps), STAGE_BYTES);
            tma_load_2d(sb + SMEM_A(ps), &tmx, (kc + 2) * KC, m0, sb + SMEM_FULL(ps));
            tma_load_2d(sb + SMEM_B(ps), &tmw, (kc + 2) * KC, n0, sb + SMEM_FULL(ps));
            if (++ps == NSTAGES) { ps = 0; pph ^= 1; }
        }

        MBARRIER_WAIT_PARITY(sb + SMEM_FULL(cs), cph);
        uint32_t sA = sb + SMEM_A(cs);
        uint32_t sB = sb + SMEM_B(cs);

#pragma unroll
        for (int k8 = 0; k8 < 4; k8++) {
            const uint32_t kb4 = k8 * 32;
            uint32_t af[4][4], bf[4][2];
            const uint32_t ca = (kb4 + a_k4) ^ a_swz;
            const uint32_t cb = (kb4 + b_k4) ^ b_swz;
#pragma unroll
            for (int i = 0; i < 4; i++)
                ldsm4(af[i], sA + (a_row + i * 16) * 128 + ca);
#pragma unroll
            for (int p = 0; p < 2; p++) {
                uint32_t t[4];
                ldsm4(t, sB + (b_row + p * 16) * 128 + cb);
                bf[2 * p][0]     = t[0];
                bf[2 * p][1]     = t[1];
                bf[2 * p + 1][0] = t[2];
                bf[2 * p + 1][1] = t[3];
            }
#pragma unroll
            for (int i = 0; i < 4; i++)
#pragma unroll
                for (int j = 0; j < 4; j++)
                    mma_tf32(acc[i][j], af[i], bf[j]);
        }

        if (lid == 0) MBARRIER_ARRIVE(sb + SMEM_EMPTY(cs));
        if (++cs == NSTAGES) { cs = 0; cph ^= 1; }
    }

    // --- epilogue: acc + bias -> out ---
#pragma unroll
    for (int j = 0; j < 4; j++) {
        int col = n0 + wn0 + j * 8 + qid * 2;
        float2 bb = *(const float2*)(bias + col);
#pragma unroll
        for (int i = 0; i < 4; i++) {
            int row = m0 + wm0 + i * 16 + gid;
            float2 v0 = make_float2(acc[i][j][0] + bb.x, acc[i][j][1] + bb.y);
            float2 v1 = make_float2(acc[i][j][2] + bb.x, acc[i][j][3] + bb.y);
            *(float2*)(out + (size_t)row * MDIM + col) = v0;
            *(float2*)(out + (size_t)(row + 8) * MDIM + col) = v1;
        }
    }
}

// ============================================================================
// Host launch
// ============================================================================
typedef CUresult (*EncodeTiledFn)(
    CUtensorMap*, CUtensorMapDataType, cuuint32_t, void*,
    const cuuint64_t*, const cuuint64_t*, const cuuint32_t*, const cuuint32_t*,
    CUtensorMapInterleave, CUtensorMapSwizzle, CUtensorMapL2promotion,
    CUtensorMapFloatOOBfill);

static void make_map_2d(CUtensorMap* tm, const void* ptr,
                        unsigned long long d0, unsigned long long d1) {
    EncodeTiledFn fn = nullptr;
    cudaDriverEntryPointQueryResult qr;
    cudaGetDriverEntryPoint("cuTensorMapEncodeTiled", (void**)&fn,
                            cudaEnableDefault, &qr);
    cuuint64_t dims[2]    = {d0, d1};
    cuuint64_t strides[1] = {d0 * sizeof(float)};
    cuuint32_t box[2]     = {KC, TILE_M};
    cuuint32_t es[2]      = {1, 1};
    fn(tm, CU_TENSOR_MAP_DATA_TYPE_FLOAT32, 2, (void*)ptr, dims, strides, box, es,
       CU_TENSOR_MAP_INTERLEAVE_NONE, CU_TENSOR_MAP_SWIZZLE_128B,
       CU_TENSOR_MAP_L2_PROMOTION_L2_128B, CU_TENSOR_MAP_FLOAT_OOB_FILL_NONE);
}

extern "C" void kernel_launch(void* const* d_in, const int* in_sizes, int n_in,
                              void* d_out, int out_size) {
    const float* x = (const float*)d_in[0];
    const float* W = (const float*)d_in[1];
    const float* b = (const float*)d_in[2];
    const float* A = (const float*)d_in[3];
    const float* B = (const float*)d_in[4];
    float* out = (float*)d_out;
    int T = in_sizes[0] / KDIM;

    void* weff_ptr = nullptr;
    cudaGetSymbolAddress(&weff_ptr, g_Weff);

    int prep_blocks = (MDIM / PREP_MT) * (KDIM / PREP_KT);   // 128 * 4 = 512
    weff_prep_kernel<<<prep_blocks, 256>>>(W, A, B, (uint32_t*)weff_ptr);

    CUtensorMap tmx, tmw;
    make_map_2d(&tmx, x, KDIM, (unsigned long long)T);
    make_map_2d(&tmw, weff_ptr, KDIM, MDIM);

    cudaFuncSetAttribute(lora_gemm_kernel,
                         cudaFuncAttributeMaxDynamicSharedMemorySize, SMEM_BYTES);

    dim3 grid(MDIM / TILE_N, T / TILE_M);   // (32, 64) — n fastest for L2 reuse
    lora_gemm_kernel<<<grid, NTHREADS, SMEM_BYTES>>>(tmx, tmw, b, out);
}